// round 12
// baseline (speedup 1.0000x reference)
#include <cuda_runtime.h>
#include <cuda_fp16.h>
#include <cstdint>

#define N_NODES 40000
#define DIMF    128
#define N_EDGES 640000
#define CAP     96            // max supported in-degree (Poisson(16): P(>=96)~0)

// ---- scratch (no allocs allowed) ----
__device__ int    g_cur[N_NODES];           // sort cursors == degree after sort
__device__ int    g_esrc[N_NODES * CAP];    // src ids, padded CSR (15.4 MB)
__device__ float  g_cnt[N_NODES];           // in-degree (float, for GEMM)
__device__ float  g_agg[N_NODES * DIMF];    // neighbor-sum buffer (fp32)
__device__ float  g_h[N_NODES * DIMF];      // layer-1 output (fp32)
__device__ __half g_xh[N_NODES * DIMF];     // fp16 shadow of x
__device__ __half g_hh[N_NODES * DIMF];     // fp16 shadow of h

// ---------------------------------------------------------------------------
// prep: x -> fp16 shadow; zero cursors.
// ---------------------------------------------------------------------------
__global__ void prep_kernel(const float* __restrict__ x) {
    int i = blockIdx.x * blockDim.x + threadIdx.x;      // float4 index
    const int tot4 = N_NODES * DIMF / 4;
    if (i < tot4) {
        float4 v = reinterpret_cast<const float4*>(x)[i];
        __half2 h01 = __floats2half2_rn(v.x, v.y);
        __half2 h23 = __floats2half2_rn(v.z, v.w);
        uint2 packed;
        packed.x = *reinterpret_cast<uint32_t*>(&h01);
        packed.y = *reinterpret_cast<uint32_t*>(&h23);
        reinterpret_cast<uint2*>(g_xh)[i] = packed;
    }
    if (i < N_NODES) g_cur[i] = 0;
}

// ---------------------------------------------------------------------------
// padded-CSR counting sort. Cursor end-value == degree (no hist, no scan).
// ---------------------------------------------------------------------------
__global__ void sort_kernel(const int* __restrict__ ei) {
    int e = blockIdx.x * blockDim.x + threadIdx.x;
    if (e >= N_EDGES) return;
    int s = ei[e];
    int d = ei[N_EDGES + e];
    if ((unsigned)s >= N_NODES || (unsigned)d >= N_NODES) return;
    int pos = atomicAdd(&g_cur[d], 1);
    if (pos < CAP) g_esrc[d * CAP + pos] = s;
}

// ---------------------------------------------------------------------------
// aggregate (gather): one warp per dst node; batch-32 coalesced index loads,
// 8 independent fp16 LDG.64 chains (MLP=8); one 512B store. Zero atomics.
// ---------------------------------------------------------------------------
__global__ __launch_bounds__(256) void agg_kernel(const __half* __restrict__ feat16) {
    const int w    = blockIdx.x * 8 + (threadIdx.x >> 5);
    const int lane = threadIdx.x & 31;
    if (w >= N_NODES) return;

    const int degc  = g_cur[w];
    const int deg   = min(degc, CAP);
    const int start = w * CAP;
    if (lane == 0) g_cnt[w] = (float)degc;

    float4 a0 = make_float4(0.f, 0.f, 0.f, 0.f), a1 = a0, a2 = a0, a3 = a0,
           a4 = a0, a5 = a0, a6 = a0, a7 = a0;

    for (int base = 0; base < deg; base += 32) {
        const int n = min(32, deg - base);
        int idx = __ldg(&g_esrc[start + base + lane]);

        int j = 0;
        const int full = n & ~7;
#pragma unroll 1
        for (; j < full; j += 8) {
            int s0 = __shfl_sync(0xffffffffu, idx, j + 0);
            int s1 = __shfl_sync(0xffffffffu, idx, j + 1);
            int s2 = __shfl_sync(0xffffffffu, idx, j + 2);
            int s3 = __shfl_sync(0xffffffffu, idx, j + 3);
            int s4 = __shfl_sync(0xffffffffu, idx, j + 4);
            int s5 = __shfl_sync(0xffffffffu, idx, j + 5);
            int s6 = __shfl_sync(0xffffffffu, idx, j + 6);
            int s7 = __shfl_sync(0xffffffffu, idx, j + 7);
            uint2 r0 = reinterpret_cast<const uint2*>(feat16 + (size_t)s0 * DIMF)[lane];
            uint2 r1 = reinterpret_cast<const uint2*>(feat16 + (size_t)s1 * DIMF)[lane];
            uint2 r2 = reinterpret_cast<const uint2*>(feat16 + (size_t)s2 * DIMF)[lane];
            uint2 r3 = reinterpret_cast<const uint2*>(feat16 + (size_t)s3 * DIMF)[lane];
            uint2 r4 = reinterpret_cast<const uint2*>(feat16 + (size_t)s4 * DIMF)[lane];
            uint2 r5 = reinterpret_cast<const uint2*>(feat16 + (size_t)s5 * DIMF)[lane];
            uint2 r6 = reinterpret_cast<const uint2*>(feat16 + (size_t)s6 * DIMF)[lane];
            uint2 r7 = reinterpret_cast<const uint2*>(feat16 + (size_t)s7 * DIMF)[lane];
            float2 f01, f23;
            f01 = __half22float2(*reinterpret_cast<__half2*>(&r0.x));
            f23 = __half22float2(*reinterpret_cast<__half2*>(&r0.y));
            a0.x += f01.x; a0.y += f01.y; a0.z += f23.x; a0.w += f23.y;
            f01 = __half22float2(*reinterpret_cast<__half2*>(&r1.x));
            f23 = __half22float2(*reinterpret_cast<__half2*>(&r1.y));
            a1.x += f01.x; a1.y += f01.y; a1.z += f23.x; a1.w += f23.y;
            f01 = __half22float2(*reinterpret_cast<__half2*>(&r2.x));
            f23 = __half22float2(*reinterpret_cast<__half2*>(&r2.y));
            a2.x += f01.x; a2.y += f01.y; a2.z += f23.x; a2.w += f23.y;
            f01 = __half22float2(*reinterpret_cast<__half2*>(&r3.x));
            f23 = __half22float2(*reinterpret_cast<__half2*>(&r3.y));
            a3.x += f01.x; a3.y += f01.y; a3.z += f23.x; a3.w += f23.y;
            f01 = __half22float2(*reinterpret_cast<__half2*>(&r4.x));
            f23 = __half22float2(*reinterpret_cast<__half2*>(&r4.y));
            a4.x += f01.x; a4.y += f01.y; a4.z += f23.x; a4.w += f23.y;
            f01 = __half22float2(*reinterpret_cast<__half2*>(&r5.x));
            f23 = __half22float2(*reinterpret_cast<__half2*>(&r5.y));
            a5.x += f01.x; a5.y += f01.y; a5.z += f23.x; a5.w += f23.y;
            f01 = __half22float2(*reinterpret_cast<__half2*>(&r6.x));
            f23 = __half22float2(*reinterpret_cast<__half2*>(&r6.y));
            a6.x += f01.x; a6.y += f01.y; a6.z += f23.x; a6.w += f23.y;
            f01 = __half22float2(*reinterpret_cast<__half2*>(&r7.x));
            f23 = __half22float2(*reinterpret_cast<__half2*>(&r7.y));
            a7.x += f01.x; a7.y += f01.y; a7.z += f23.x; a7.w += f23.y;
        }
#pragma unroll 1
        for (; j < n; ++j) {
            int s = __shfl_sync(0xffffffffu, idx, j);
            uint2 r = reinterpret_cast<const uint2*>(feat16 + (size_t)s * DIMF)[lane];
            float2 f01 = __half22float2(*reinterpret_cast<__half2*>(&r.x));
            float2 f23 = __half22float2(*reinterpret_cast<__half2*>(&r.y));
            a0.x += f01.x; a0.y += f01.y; a0.z += f23.x; a0.w += f23.y;
        }
    }

    float4 acc;
    acc.x = (a0.x + a1.x) + (a2.x + a3.x) + ((a4.x + a5.x) + (a6.x + a7.x));
    acc.y = (a0.y + a1.y) + (a2.y + a3.y) + ((a4.y + a5.y) + (a6.y + a7.y));
    acc.z = (a0.z + a1.z) + (a2.z + a3.z) + ((a4.z + a5.z) + (a6.z + a7.z));
    acc.w = (a0.w + a1.w) + (a2.w + a3.w) + ((a4.w + a5.w) + (a6.w + a7.w));
    reinterpret_cast<float4*>(g_agg + (size_t)w * DIMF)[lane] = acc;
}

// ---------------------------------------------------------------------------
// Tensor-core tf32 GEMM, BM=64 (625 tiles -> 1.06 waves at 4 CTAs/SM):
//   out[m][n] = relu( (1/max(cnt[m],1)) * sum_k A0[m][k]*W0[n][k]
//                    + sum_k A1[m][k]*W1[n][k] + bias[n] )
// 8 warps = 2(M)x4(N); warp tile 32x32; m16n8k8 tf32 MMA; double-buffered.
// ---------------------------------------------------------------------------
#define BM   64
#define BK   16
#define LDPA 68    // As row stride (u32)
#define LDPB 132   // Bs row stride (u32)

__device__ __forceinline__ uint32_t f2tf32(float v) {
    uint32_t t;
    asm("cvt.rna.tf32.f32 %0, %1;" : "=r"(t) : "f"(v));
    return t;
}

__global__ __launch_bounds__(256, 4) void gemm_tc_kernel(
        const float* A0, const float* __restrict__ A1,
        const float* __restrict__ cnt,
        const float* __restrict__ W0, const float* __restrict__ W1,
        const float* __restrict__ bias, float* __restrict__ out,
        __half* out16) {
    __shared__ uint32_t As[2][BK * LDPA];
    __shared__ uint32_t Bs[2][BK * LDPB];

    const int tid   = threadIdx.x;
    const int m0    = blockIdx.x * BM;
    const int lane  = tid & 31;
    const int warp  = tid >> 5;
    const int warpM = warp & 1;        // 0..1 -> 32 rows each
    const int warpN = warp >> 1;       // 0..3 -> 32 cols each
    const int lr    = lane >> 2;       // 0..7
    const int lc    = lane & 3;        // 0..3

    const int r0 = tid >> 2;           // 0..63 (A row / W row)
    const int q  = tid & 3;            // 0..3 (16B k-chunk)

    const int gm0 = m0 + r0;
    const float s0 = (gm0 < N_NODES) ? __frcp_rn(fmaxf(__ldg(&cnt[gm0]), 1.f)) : 0.f;

    float acc[2][4][4];   // [m-tile][n-tile][frag]
#pragma unroll
    for (int i = 0; i < 2; ++i)
#pragma unroll
        for (int j = 0; j < 4; ++j)
#pragma unroll
            for (int f = 0; f < 4; ++f) acc[i][j][f] = 0.f;

    const float4 f4z = make_float4(0.f, 0.f, 0.f, 0.f);
    float4 a0r, b0r, b1r;

    auto load_tile = [&](int kt, float4& av0, float4& bv0, float4& bv1) {
        const float* A = (kt < 8) ? A0 : A1;
        const float* W = (kt < 8) ? W0 : W1;
        const float sc0 = (kt < 8) ? s0 : 1.f;
        const int k0 = (kt & 7) * BK + q * 4;
        av0 = (gm0 < N_NODES) ? *reinterpret_cast<const float4*>(A + (size_t)gm0 * DIMF + k0) : f4z;
        av0.x *= sc0; av0.y *= sc0; av0.z *= sc0; av0.w *= sc0;
        bv0 = *reinterpret_cast<const float4*>(W + (size_t)r0 * DIMF + k0);         // W rows 0..63
        bv1 = *reinterpret_cast<const float4*>(W + (size_t)(r0 + 64) * DIMF + k0);  // W rows 64..127
    };

    auto store_tile = [&](int buf) {
        const int kb = q * 4;
        As[buf][(kb + 0) * LDPA + r0] = f2tf32(a0r.x);
        As[buf][(kb + 1) * LDPA + r0] = f2tf32(a0r.y);
        As[buf][(kb + 2) * LDPA + r0] = f2tf32(a0r.z);
        As[buf][(kb + 3) * LDPA + r0] = f2tf32(a0r.w);
        Bs[buf][(kb + 0) * LDPB + r0] = f2tf32(b0r.x);
        Bs[buf][(kb + 1) * LDPB + r0] = f2tf32(b0r.y);
        Bs[buf][(kb + 2) * LDPB + r0] = f2tf32(b0r.z);
        Bs[buf][(kb + 3) * LDPB + r0] = f2tf32(b0r.w);
        Bs[buf][(kb + 0) * LDPB + r0 + 64] = f2tf32(b1r.x);
        Bs[buf][(kb + 1) * LDPB + r0 + 64] = f2tf32(b1r.y);
        Bs[buf][(kb + 2) * LDPB + r0 + 64] = f2tf32(b1r.z);
        Bs[buf][(kb + 3) * LDPB + r0 + 64] = f2tf32(b1r.w);
    };

    load_tile(0, a0r, b0r, b1r);
    store_tile(0);
    __syncthreads();

#pragma unroll 1
    for (int kt = 0; kt < 16; ++kt) {
        const int buf = kt & 1;
        if (kt < 15) load_tile(kt + 1, a0r, b0r, b1r);

#pragma unroll
        for (int s = 0; s < BK; s += 8) {
            uint32_t bf0[4], bf1[4];
#pragma unroll
            for (int nt = 0; nt < 4; ++nt) {
                const int n = warpN * 32 + nt * 8 + lr;
                bf0[nt] = Bs[buf][(s + lc) * LDPB + n];
                bf1[nt] = Bs[buf][(s + lc + 4) * LDPB + n];
            }
#pragma unroll
            for (int mt = 0; mt < 2; ++mt) {
                const int m = warpM * 32 + mt * 16 + lr;
                uint32_t a0 = As[buf][(s + lc) * LDPA + m];
                uint32_t a1 = As[buf][(s + lc) * LDPA + m + 8];
                uint32_t a2 = As[buf][(s + lc + 4) * LDPA + m];
                uint32_t a3 = As[buf][(s + lc + 4) * LDPA + m + 8];
#pragma unroll
                for (int nt = 0; nt < 4; ++nt) {
                    asm volatile(
                        "mma.sync.aligned.m16n8k8.row.col.f32.tf32.tf32.f32 "
                        "{%0,%1,%2,%3}, {%4,%5,%6,%7}, {%8,%9}, {%0,%1,%2,%3};"
                        : "+f"(acc[mt][nt][0]), "+f"(acc[mt][nt][1]),
                          "+f"(acc[mt][nt][2]), "+f"(acc[mt][nt][3])
                        : "r"(a0), "r"(a1), "r"(a2), "r"(a3),
                          "r"(bf0[nt]), "r"(bf1[nt]));
                }
            }
        }

        if (kt < 15) {
            store_tile(buf ^ 1);
            __syncthreads();
        }
    }

    // epilogue: + bias, relu; optional fp16 shadow store
#pragma unroll
    for (int nt = 0; nt < 4; ++nt) {
        const int n = warpN * 32 + nt * 8 + 2 * lc;
        const float bv0 = __ldg(&bias[n]);
        const float bv1 = __ldg(&bias[n + 1]);
#pragma unroll
        for (int mt = 0; mt < 2; ++mt) {
            const int r = m0 + warpM * 32 + mt * 16 + lr;
            if (r < N_NODES) {
                float2 v;
                v.x = fmaxf(acc[mt][nt][0] + bv0, 0.f);
                v.y = fmaxf(acc[mt][nt][1] + bv1, 0.f);
                *reinterpret_cast<float2*>(out + (size_t)r * DIMF + n) = v;
                if (out16)
                    *reinterpret_cast<__half2*>(out16 + (size_t)r * DIMF + n) =
                        __floats2half2_rn(v.x, v.y);
            }
            if (r + 8 < N_NODES) {
                float2 v;
                v.x = fmaxf(acc[mt][nt][2] + bv0, 0.f);
                v.y = fmaxf(acc[mt][nt][3] + bv1, 0.f);
                *reinterpret_cast<float2*>(out + (size_t)(r + 8) * DIMF + n) = v;
                if (out16)
                    *reinterpret_cast<__half2*>(out16 + (size_t)(r + 8) * DIMF + n) =
                        __floats2half2_rn(v.x, v.y);
            }
        }
    }
}

// ---------------------------------------------------------------------------
// launch
// ---------------------------------------------------------------------------
extern "C" void kernel_launch(void* const* d_in, const int* in_sizes, int n_in,
                              void* d_out, int out_size) {
    const float* x   = (const float*)d_in[0];
    const int*   ei  = (const int*)d_in[1];
    const float* W1l = (const float*)d_in[2];
    const float* b1l = (const float*)d_in[3];
    const float* W1r = (const float*)d_in[4];
    const float* W2l = (const float*)d_in[5];
    const float* b2l = (const float*)d_in[6];
    const float* W2r = (const float*)d_in[7];
    float* out = (float*)d_out;

    const int tot4      = N_NODES * DIMF / 4;
    const int prep_grid = (tot4 + 255) / 256;
    const int edge_grid = (N_EDGES + 255) / 256;
    const int agg_grid  = (N_NODES + 7) / 8;              // warp per node
    const int gemm_grid = (N_NODES + BM - 1) / BM;        // 625

    static float*  p_agg = nullptr;
    static float*  p_h   = nullptr;
    static float*  p_cnt = nullptr;
    static __half* p_xh  = nullptr;
    static __half* p_hh  = nullptr;
    if (!p_agg) {
        cudaGetSymbolAddress((void**)&p_agg, g_agg);
        cudaGetSymbolAddress((void**)&p_h,   g_h);
        cudaGetSymbolAddress((void**)&p_cnt, g_cnt);
        cudaGetSymbolAddress((void**)&p_xh,  g_xh);
        cudaGetSymbolAddress((void**)&p_hh,  g_hh);
    }

    // ---- prep + padded-CSR build (no hist, no scan) ----
    prep_kernel<<<prep_grid, 256>>>(x);
    sort_kernel<<<edge_grid, 256>>>(ei);

    // ---- layer 1 ----
    agg_kernel<<<agg_grid, 256>>>(p_xh);
    gemm_tc_kernel<<<gemm_grid, 256>>>(p_agg, x, p_cnt, W1l, W1r, b1l, p_h, p_hh);

    // ---- layer 2 ----
    agg_kernel<<<agg_grid, 256>>>(p_hh);
    gemm_tc_kernel<<<gemm_grid, 256>>>(p_agg, p_h, p_cnt, W2l, W2r, b2l, out, nullptr);
}

// round 13
// speedup vs baseline: 1.2225x; 1.2225x over previous
#include <cuda_runtime.h>
#include <cuda_fp16.h>
#include <cstdint>

#define N_NODES 40000
#define DIMF    128
#define N_EDGES 640000
#define CAP     96            // max supported in-degree (Poisson(16): P(>=96)~0)

// ---- scratch (no allocs allowed) ----
__device__ int    g_cur[N_NODES];           // sort cursors == degree after sort
__device__ int    g_esrc[N_NODES * CAP];    // src ids, padded CSR (15.4 MB)
__device__ float  g_cnt[N_NODES];           // in-degree (float, for GEMM)
__device__ float  g_agg[N_NODES * DIMF];    // neighbor-sum buffer (fp32)
__device__ float  g_h[N_NODES * DIMF];      // layer-1 output (fp32)
__device__ __half g_xh[N_NODES * DIMF];     // fp16 shadow of x
__device__ __half g_hh[N_NODES * DIMF];     // fp16 shadow of h

// ---------------------------------------------------------------------------
// prep: x -> fp16 shadow; zero cursors.
// ---------------------------------------------------------------------------
__global__ void prep_kernel(const float* __restrict__ x) {
    int i = blockIdx.x * blockDim.x + threadIdx.x;      // float4 index
    const int tot4 = N_NODES * DIMF / 4;
    if (i < tot4) {
        float4 v = reinterpret_cast<const float4*>(x)[i];
        __half2 h01 = __floats2half2_rn(v.x, v.y);
        __half2 h23 = __floats2half2_rn(v.z, v.w);
        uint2 packed;
        packed.x = *reinterpret_cast<uint32_t*>(&h01);
        packed.y = *reinterpret_cast<uint32_t*>(&h23);
        reinterpret_cast<uint2*>(g_xh)[i] = packed;
    }
    if (i < N_NODES) g_cur[i] = 0;
}

// ---------------------------------------------------------------------------
// padded-CSR counting sort. Cursor end-value == degree (no hist, no scan).
// ---------------------------------------------------------------------------
__global__ void sort_kernel(const int* __restrict__ ei) {
    int e = blockIdx.x * blockDim.x + threadIdx.x;
    if (e >= N_EDGES) return;
    int s = ei[e];
    int d = ei[N_EDGES + e];
    if ((unsigned)s >= N_NODES || (unsigned)d >= N_NODES) return;
    int pos = atomicAdd(&g_cur[d], 1);
    if (pos < CAP) g_esrc[d * CAP + pos] = s;
}

// ---------------------------------------------------------------------------
// aggregate (gather): one warp per dst node; batch-32 coalesced index loads,
// 8 independent fp16 LDG.64 chains (MLP=8); one 512B store. Zero atomics.
// ---------------------------------------------------------------------------
__global__ __launch_bounds__(256) void agg_kernel(const __half* __restrict__ feat16) {
    const int w    = blockIdx.x * 8 + (threadIdx.x >> 5);
    const int lane = threadIdx.x & 31;
    if (w >= N_NODES) return;

    const int degc  = g_cur[w];
    const int deg   = min(degc, CAP);
    const int start = w * CAP;
    if (lane == 0) g_cnt[w] = (float)degc;

    float4 a0 = make_float4(0.f, 0.f, 0.f, 0.f), a1 = a0, a2 = a0, a3 = a0,
           a4 = a0, a5 = a0, a6 = a0, a7 = a0;

    for (int base = 0; base < deg; base += 32) {
        const int n = min(32, deg - base);
        int idx = __ldg(&g_esrc[start + base + lane]);

        int j = 0;
        const int full = n & ~7;
#pragma unroll 1
        for (; j < full; j += 8) {
            int s0 = __shfl_sync(0xffffffffu, idx, j + 0);
            int s1 = __shfl_sync(0xffffffffu, idx, j + 1);
            int s2 = __shfl_sync(0xffffffffu, idx, j + 2);
            int s3 = __shfl_sync(0xffffffffu, idx, j + 3);
            int s4 = __shfl_sync(0xffffffffu, idx, j + 4);
            int s5 = __shfl_sync(0xffffffffu, idx, j + 5);
            int s6 = __shfl_sync(0xffffffffu, idx, j + 6);
            int s7 = __shfl_sync(0xffffffffu, idx, j + 7);
            uint2 r0 = reinterpret_cast<const uint2*>(feat16 + (size_t)s0 * DIMF)[lane];
            uint2 r1 = reinterpret_cast<const uint2*>(feat16 + (size_t)s1 * DIMF)[lane];
            uint2 r2 = reinterpret_cast<const uint2*>(feat16 + (size_t)s2 * DIMF)[lane];
            uint2 r3 = reinterpret_cast<const uint2*>(feat16 + (size_t)s3 * DIMF)[lane];
            uint2 r4 = reinterpret_cast<const uint2*>(feat16 + (size_t)s4 * DIMF)[lane];
            uint2 r5 = reinterpret_cast<const uint2*>(feat16 + (size_t)s5 * DIMF)[lane];
            uint2 r6 = reinterpret_cast<const uint2*>(feat16 + (size_t)s6 * DIMF)[lane];
            uint2 r7 = reinterpret_cast<const uint2*>(feat16 + (size_t)s7 * DIMF)[lane];
            float2 f01, f23;
            f01 = __half22float2(*reinterpret_cast<__half2*>(&r0.x));
            f23 = __half22float2(*reinterpret_cast<__half2*>(&r0.y));
            a0.x += f01.x; a0.y += f01.y; a0.z += f23.x; a0.w += f23.y;
            f01 = __half22float2(*reinterpret_cast<__half2*>(&r1.x));
            f23 = __half22float2(*reinterpret_cast<__half2*>(&r1.y));
            a1.x += f01.x; a1.y += f01.y; a1.z += f23.x; a1.w += f23.y;
            f01 = __half22float2(*reinterpret_cast<__half2*>(&r2.x));
            f23 = __half22float2(*reinterpret_cast<__half2*>(&r2.y));
            a2.x += f01.x; a2.y += f01.y; a2.z += f23.x; a2.w += f23.y;
            f01 = __half22float2(*reinterpret_cast<__half2*>(&r3.x));
            f23 = __half22float2(*reinterpret_cast<__half2*>(&r3.y));
            a3.x += f01.x; a3.y += f01.y; a3.z += f23.x; a3.w += f23.y;
            f01 = __half22float2(*reinterpret_cast<__half2*>(&r4.x));
            f23 = __half22float2(*reinterpret_cast<__half2*>(&r4.y));
            a4.x += f01.x; a4.y += f01.y; a4.z += f23.x; a4.w += f23.y;
            f01 = __half22float2(*reinterpret_cast<__half2*>(&r5.x));
            f23 = __half22float2(*reinterpret_cast<__half2*>(&r5.y));
            a5.x += f01.x; a5.y += f01.y; a5.z += f23.x; a5.w += f23.y;
            f01 = __half22float2(*reinterpret_cast<__half2*>(&r6.x));
            f23 = __half22float2(*reinterpret_cast<__half2*>(&r6.y));
            a6.x += f01.x; a6.y += f01.y; a6.z += f23.x; a6.w += f23.y;
            f01 = __half22float2(*reinterpret_cast<__half2*>(&r7.x));
            f23 = __half22float2(*reinterpret_cast<__half2*>(&r7.y));
            a7.x += f01.x; a7.y += f01.y; a7.z += f23.x; a7.w += f23.y;
        }
#pragma unroll 1
        for (; j < n; ++j) {
            int s = __shfl_sync(0xffffffffu, idx, j);
            uint2 r = reinterpret_cast<const uint2*>(feat16 + (size_t)s * DIMF)[lane];
            float2 f01 = __half22float2(*reinterpret_cast<__half2*>(&r.x));
            float2 f23 = __half22float2(*reinterpret_cast<__half2*>(&r.y));
            a0.x += f01.x; a0.y += f01.y; a0.z += f23.x; a0.w += f23.y;
        }
    }

    float4 acc;
    acc.x = (a0.x + a1.x) + (a2.x + a3.x) + ((a4.x + a5.x) + (a6.x + a7.x));
    acc.y = (a0.y + a1.y) + (a2.y + a3.y) + ((a4.y + a5.y) + (a6.y + a7.y));
    acc.z = (a0.z + a1.z) + (a2.z + a3.z) + ((a4.z + a5.z) + (a6.z + a7.z));
    acc.w = (a0.w + a1.w) + (a2.w + a3.w) + ((a4.w + a5.w) + (a6.w + a7.w));
    reinterpret_cast<float4*>(g_agg + (size_t)w * DIMF)[lane] = acc;
}

// ---------------------------------------------------------------------------
// fp16 tensor-core GEMM (m16n8k16), BM=128, K-major smem tiles:
//   out[m][n] = relu( (1/max(cnt[m],1)) * sum_k A0[m][k]*W0[n][k]
//                    + sum_k A1[m][k]*W1[n][k] + bias[n] )
// A0 = fp32 agg (scaled+cvt at load); A1 = fp16 shadow (direct).
// Tiles As[m][k], Bs[n][k], row stride 24 halves (48B) -> conflict-free.
// 8 warps = 2(M)x4(N); warp tile 64x32; double-buffered, 1 sync/tile.
// ---------------------------------------------------------------------------
#define BM  128
#define LDH 24     // halves per tile row (48B)

__global__ __launch_bounds__(256, 2) void gemm_tc_kernel(
        const float* A0, const __half* __restrict__ A1h,
        const float* __restrict__ cnt,
        const float* __restrict__ W0, const float* __restrict__ W1,
        const float* __restrict__ bias, float* __restrict__ out,
        __half* out16) {
    __shared__ __half As[2][BM * LDH];
    __shared__ __half Bs[2][128 * LDH];

    const int tid   = threadIdx.x;
    const int m0    = blockIdx.x * BM;
    const int lane  = tid & 31;
    const int warp  = tid >> 5;
    const int warpM = warp & 1;        // 0..1 -> 64 rows each
    const int warpN = warp >> 1;       // 0..3 -> 32 cols each
    const int lr    = lane >> 2;       // 0..7  (groupID)
    const int lc    = lane & 3;        // 0..3  (threadID-in-group)

    const int r0 = tid >> 2;           // 0..63; handles rows r0 and r0+64
    const int q  = tid & 3;            // 0..3  (4-half k-chunk)

    const int gm0 = m0 + r0, gm1 = m0 + r0 + 64;
    const float s0 = (gm0 < N_NODES) ? __frcp_rn(fmaxf(__ldg(&cnt[gm0]), 1.f)) : 0.f;
    const float s1 = (gm1 < N_NODES) ? __frcp_rn(fmaxf(__ldg(&cnt[gm1]), 1.f)) : 0.f;

    float acc[4][4][4];   // [m-tile][n-tile][frag]
#pragma unroll
    for (int i = 0; i < 4; ++i)
#pragma unroll
        for (int j = 0; j < 4; ++j)
#pragma unroll
            for (int f = 0; f < 4; ++f) acc[i][j][f] = 0.f;

    uint2 aP0, aP1, bP0, bP1;   // packed 4 halves each

    auto packf4 = [](float4 v) {
        __half2 h01 = __floats2half2_rn(v.x, v.y);
        __half2 h23 = __floats2half2_rn(v.z, v.w);
        uint2 r;
        r.x = *reinterpret_cast<uint32_t*>(&h01);
        r.y = *reinterpret_cast<uint32_t*>(&h23);
        return r;
    };

    auto load_tile = [&](int kt) {
        const int k0 = (kt & 7) * 16 + q * 4;
        if (kt < 8) {
            float4 v0 = (gm0 < N_NODES)
                ? *reinterpret_cast<const float4*>(A0 + (size_t)gm0 * DIMF + k0)
                : make_float4(0.f, 0.f, 0.f, 0.f);
            float4 v1 = (gm1 < N_NODES)
                ? *reinterpret_cast<const float4*>(A0 + (size_t)gm1 * DIMF + k0)
                : make_float4(0.f, 0.f, 0.f, 0.f);
            v0.x *= s0; v0.y *= s0; v0.z *= s0; v0.w *= s0;
            v1.x *= s1; v1.y *= s1; v1.z *= s1; v1.w *= s1;
            aP0 = packf4(v0);
            aP1 = packf4(v1);
            bP0 = packf4(*reinterpret_cast<const float4*>(W0 + (size_t)r0 * DIMF + k0));
            bP1 = packf4(*reinterpret_cast<const float4*>(W0 + (size_t)(r0 + 64) * DIMF + k0));
        } else {
            aP0 = (gm0 < N_NODES)
                ? *reinterpret_cast<const uint2*>(A1h + (size_t)gm0 * DIMF + k0)
                : make_uint2(0u, 0u);
            aP1 = (gm1 < N_NODES)
                ? *reinterpret_cast<const uint2*>(A1h + (size_t)gm1 * DIMF + k0)
                : make_uint2(0u, 0u);
            bP0 = packf4(*reinterpret_cast<const float4*>(W1 + (size_t)r0 * DIMF + k0));
            bP1 = packf4(*reinterpret_cast<const float4*>(W1 + (size_t)(r0 + 64) * DIMF + k0));
        }
    };

    auto store_tile = [&](int buf) {
        *reinterpret_cast<uint2*>(&As[buf][r0 * LDH + q * 4])        = aP0;
        *reinterpret_cast<uint2*>(&As[buf][(r0 + 64) * LDH + q * 4]) = aP1;
        *reinterpret_cast<uint2*>(&Bs[buf][r0 * LDH + q * 4])        = bP0;
        *reinterpret_cast<uint2*>(&Bs[buf][(r0 + 64) * LDH + q * 4]) = bP1;
    };

    load_tile(0);
    store_tile(0);
    __syncthreads();

#pragma unroll 1
    for (int kt = 0; kt < 16; ++kt) {
        const int buf = kt & 1;
        if (kt < 15) load_tile(kt + 1);   // LDG hides under MMA

        // B fragments (4 n-tiles)
        uint32_t bf0[4], bf1[4];
#pragma unroll
        for (int nt = 0; nt < 4; ++nt) {
            const int n = warpN * 32 + nt * 8 + lr;
            bf0[nt] = *reinterpret_cast<const uint32_t*>(&Bs[buf][n * LDH + 2 * lc]);
            bf1[nt] = *reinterpret_cast<const uint32_t*>(&Bs[buf][n * LDH + 2 * lc + 8]);
        }
#pragma unroll
        for (int mt = 0; mt < 4; ++mt) {
            const int m = warpM * 64 + mt * 16 + lr;
            uint32_t a0 = *reinterpret_cast<const uint32_t*>(&As[buf][m * LDH + 2 * lc]);
            uint32_t a1 = *reinterpret_cast<const uint32_t*>(&As[buf][(m + 8) * LDH + 2 * lc]);
            uint32_t a2 = *reinterpret_cast<const uint32_t*>(&As[buf][m * LDH + 2 * lc + 8]);
            uint32_t a3 = *reinterpret_cast<const uint32_t*>(&As[buf][(m + 8) * LDH + 2 * lc + 8]);
#pragma unroll
            for (int nt = 0; nt < 4; ++nt) {
                asm volatile(
                    "mma.sync.aligned.m16n8k16.row.col.f32.f16.f16.f32 "
                    "{%0,%1,%2,%3}, {%4,%5,%6,%7}, {%8,%9}, {%0,%1,%2,%3};"
                    : "+f"(acc[mt][nt][0]), "+f"(acc[mt][nt][1]),
                      "+f"(acc[mt][nt][2]), "+f"(acc[mt][nt][3])
                    : "r"(a0), "r"(a1), "r"(a2), "r"(a3),
                      "r"(bf0[nt]), "r"(bf1[nt]));
            }
        }

        if (kt < 15) {
            store_tile(buf ^ 1);
            __syncthreads();
        }
    }

    // epilogue: + bias, relu; optional fp16 shadow store
#pragma unroll
    for (int nt = 0; nt < 4; ++nt) {
        const int n = warpN * 32 + nt * 8 + 2 * lc;
        const float bv0 = __ldg(&bias[n]);
        const float bv1 = __ldg(&bias[n + 1]);
#pragma unroll
        for (int mt = 0; mt < 4; ++mt) {
            const int r = m0 + warpM * 64 + mt * 16 + lr;
            if (r < N_NODES) {
                float2 v;
                v.x = fmaxf(acc[mt][nt][0] + bv0, 0.f);
                v.y = fmaxf(acc[mt][nt][1] + bv1, 0.f);
                *reinterpret_cast<float2*>(out + (size_t)r * DIMF + n) = v;
                if (out16)
                    *reinterpret_cast<__half2*>(out16 + (size_t)r * DIMF + n) =
                        __floats2half2_rn(v.x, v.y);
            }
            if (r + 8 < N_NODES) {
                float2 v;
                v.x = fmaxf(acc[mt][nt][2] + bv0, 0.f);
                v.y = fmaxf(acc[mt][nt][3] + bv1, 0.f);
                *reinterpret_cast<float2*>(out + (size_t)(r + 8) * DIMF + n) = v;
                if (out16)
                    *reinterpret_cast<__half2*>(out16 + (size_t)(r + 8) * DIMF + n) =
                        __floats2half2_rn(v.x, v.y);
            }
        }
    }
}

// ---------------------------------------------------------------------------
// launch
// ---------------------------------------------------------------------------
extern "C" void kernel_launch(void* const* d_in, const int* in_sizes, int n_in,
                              void* d_out, int out_size) {
    const float* x   = (const float*)d_in[0];
    const int*   ei  = (const int*)d_in[1];
    const float* W1l = (const float*)d_in[2];
    const float* b1l = (const float*)d_in[3];
    const float* W1r = (const float*)d_in[4];
    const float* W2l = (const float*)d_in[5];
    const float* b2l = (const float*)d_in[6];
    const float* W2r = (const float*)d_in[7];
    float* out = (float*)d_out;

    const int tot4      = N_NODES * DIMF / 4;
    const int prep_grid = (tot4 + 255) / 256;
    const int edge_grid = (N_EDGES + 255) / 256;
    const int agg_grid  = (N_NODES + 7) / 8;              // warp per node
    const int gemm_grid = (N_NODES + BM - 1) / BM;        // 313

    static float*  p_agg = nullptr;
    static float*  p_h   = nullptr;
    static float*  p_cnt = nullptr;
    static __half* p_xh  = nullptr;
    static __half* p_hh  = nullptr;
    if (!p_agg) {
        cudaGetSymbolAddress((void**)&p_agg, g_agg);
        cudaGetSymbolAddress((void**)&p_h,   g_h);
        cudaGetSymbolAddress((void**)&p_cnt, g_cnt);
        cudaGetSymbolAddress((void**)&p_xh,  g_xh);
        cudaGetSymbolAddress((void**)&p_hh,  g_hh);
    }

    // ---- prep + padded-CSR build (no hist, no scan) ----
    prep_kernel<<<prep_grid, 256>>>(x);
    sort_kernel<<<edge_grid, 256>>>(ei);

    // ---- layer 1 ----
    agg_kernel<<<agg_grid, 256>>>(p_xh);
    gemm_tc_kernel<<<gemm_grid, 256>>>(p_agg, p_xh, p_cnt, W1l, W1r, b1l, p_h, p_hh);

    // ---- layer 2 ----
    agg_kernel<<<agg_grid, 256>>>(p_hh);
    gemm_tc_kernel<<<gemm_grid, 256>>>(p_agg, p_hh, p_cnt, W2l, W2r, b2l, out, nullptr);
}

// round 14
// speedup vs baseline: 1.5055x; 1.2315x over previous
#include <cuda_runtime.h>
#include <cuda_fp16.h>
#include <cstdint>

#define N_NODES 40000
#define DIMF    128
#define N_EDGES 640000
#define CAP     96            // max supported in-degree (Poisson(16): P(>=96)~0)

// ---- scratch (no allocs allowed) ----
__device__ int    g_cur[N_NODES];           // sort cursors == degree after sort
__device__ int    g_esrc[N_NODES * CAP];    // src ids, padded CSR (15.4 MB)
__device__ __half g_mh[N_NODES * DIMF];     // fp16 neighbor-MEAN (GEMM A0)
__device__ __half g_xh[N_NODES * DIMF];     // fp16 shadow of x
__device__ __half g_hh[N_NODES * DIMF];     // fp16 shadow of h
__device__ __half g_wh[4 * DIMF * DIMF];    // fp16 weights: W1l, W1r, W2l, W2r

// ---------------------------------------------------------------------------
// prep: x -> fp16 shadow; zero cursors.
// ---------------------------------------------------------------------------
__global__ void prep_kernel(const float* __restrict__ x) {
    int i = blockIdx.x * blockDim.x + threadIdx.x;      // float4 index
    const int tot4 = N_NODES * DIMF / 4;
    if (i < tot4) {
        float4 v = reinterpret_cast<const float4*>(x)[i];
        __half2 h01 = __floats2half2_rn(v.x, v.y);
        __half2 h23 = __floats2half2_rn(v.z, v.w);
        uint2 packed;
        packed.x = *reinterpret_cast<uint32_t*>(&h01);
        packed.y = *reinterpret_cast<uint32_t*>(&h23);
        reinterpret_cast<uint2*>(g_xh)[i] = packed;
    }
    if (i < N_NODES) g_cur[i] = 0;
}

// convert the 4 weight matrices (128x128 fp32 each) to fp16 once
__global__ void prep_w_kernel(const float* __restrict__ w0,
                              const float* __restrict__ w1,
                              const float* __restrict__ w2,
                              const float* __restrict__ w3) {
    int i = blockIdx.x * blockDim.x + threadIdx.x;      // 8-half chunk id
    const int per = DIMF * DIMF / 8;                    // 2048 chunks/matrix
    if (i >= 4 * per) return;
    const float* src = (i < per) ? w0 : (i < 2 * per) ? w1 : (i < 3 * per) ? w2 : w3;
    int rem = i & (per - 1);
    float4 a = reinterpret_cast<const float4*>(src)[rem * 2];
    float4 b = reinterpret_cast<const float4*>(src)[rem * 2 + 1];
    __half2 h0 = __floats2half2_rn(a.x, a.y), h1 = __floats2half2_rn(a.z, a.w);
    __half2 h2 = __floats2half2_rn(b.x, b.y), h3 = __floats2half2_rn(b.z, b.w);
    uint4 p;
    p.x = *reinterpret_cast<uint32_t*>(&h0);
    p.y = *reinterpret_cast<uint32_t*>(&h1);
    p.z = *reinterpret_cast<uint32_t*>(&h2);
    p.w = *reinterpret_cast<uint32_t*>(&h3);
    reinterpret_cast<uint4*>(g_wh)[i] = p;
}

// ---------------------------------------------------------------------------
// padded-CSR counting sort. Cursor end-value == degree (no hist, no scan).
// ---------------------------------------------------------------------------
__global__ void sort_kernel(const int* __restrict__ ei) {
    int e = blockIdx.x * blockDim.x + threadIdx.x;
    if (e >= N_EDGES) return;
    int s = ei[e];
    int d = ei[N_EDGES + e];
    if ((unsigned)s >= N_NODES || (unsigned)d >= N_NODES) return;
    int pos = atomicAdd(&g_cur[d], 1);
    if (pos < CAP) g_esrc[d * CAP + pos] = s;
}

// ---------------------------------------------------------------------------
// aggregate (gather): one warp per dst node; batch-32 coalesced index loads,
// 8 independent fp16 LDG.64 chains (MLP=8). Emits fp16 MEAN directly.
// ---------------------------------------------------------------------------
__global__ __launch_bounds__(256) void agg_kernel(const __half* __restrict__ feat16) {
    const int w    = blockIdx.x * 8 + (threadIdx.x >> 5);
    const int lane = threadIdx.x & 31;
    if (w >= N_NODES) return;

    const int degc  = g_cur[w];
    const int deg   = min(degc, CAP);
    const int start = w * CAP;

    float4 a0 = make_float4(0.f, 0.f, 0.f, 0.f), a1 = a0, a2 = a0, a3 = a0,
           a4 = a0, a5 = a0, a6 = a0, a7 = a0;

    for (int base = 0; base < deg; base += 32) {
        const int n = min(32, deg - base);
        int idx = __ldg(&g_esrc[start + base + lane]);

        int j = 0;
        const int full = n & ~7;
#pragma unroll 1
        for (; j < full; j += 8) {
            int s0 = __shfl_sync(0xffffffffu, idx, j + 0);
            int s1 = __shfl_sync(0xffffffffu, idx, j + 1);
            int s2 = __shfl_sync(0xffffffffu, idx, j + 2);
            int s3 = __shfl_sync(0xffffffffu, idx, j + 3);
            int s4 = __shfl_sync(0xffffffffu, idx, j + 4);
            int s5 = __shfl_sync(0xffffffffu, idx, j + 5);
            int s6 = __shfl_sync(0xffffffffu, idx, j + 6);
            int s7 = __shfl_sync(0xffffffffu, idx, j + 7);
            uint2 r0 = reinterpret_cast<const uint2*>(feat16 + (size_t)s0 * DIMF)[lane];
            uint2 r1 = reinterpret_cast<const uint2*>(feat16 + (size_t)s1 * DIMF)[lane];
            uint2 r2 = reinterpret_cast<const uint2*>(feat16 + (size_t)s2 * DIMF)[lane];
            uint2 r3 = reinterpret_cast<const uint2*>(feat16 + (size_t)s3 * DIMF)[lane];
            uint2 r4 = reinterpret_cast<const uint2*>(feat16 + (size_t)s4 * DIMF)[lane];
            uint2 r5 = reinterpret_cast<const uint2*>(feat16 + (size_t)s5 * DIMF)[lane];
            uint2 r6 = reinterpret_cast<const uint2*>(feat16 + (size_t)s6 * DIMF)[lane];
            uint2 r7 = reinterpret_cast<const uint2*>(feat16 + (size_t)s7 * DIMF)[lane];
            float2 f01, f23;
            f01 = __half22float2(*reinterpret_cast<__half2*>(&r0.x));
            f23 = __half22float2(*reinterpret_cast<__half2*>(&r0.y));
            a0.x += f01.x; a0.y += f01.y; a0.z += f23.x; a0.w += f23.y;
            f01 = __half22float2(*reinterpret_cast<__half2*>(&r1.x));
            f23 = __half22float2(*reinterpret_cast<__half2*>(&r1.y));
            a1.x += f01.x; a1.y += f01.y; a1.z += f23.x; a1.w += f23.y;
            f01 = __half22float2(*reinterpret_cast<__half2*>(&r2.x));
            f23 = __half22float2(*reinterpret_cast<__half2*>(&r2.y));
            a2.x += f01.x; a2.y += f01.y; a2.z += f23.x; a2.w += f23.y;
            f01 = __half22float2(*reinterpret_cast<__half2*>(&r3.x));
            f23 = __half22float2(*reinterpret_cast<__half2*>(&r3.y));
            a3.x += f01.x; a3.y += f01.y; a3.z += f23.x; a3.w += f23.y;
            f01 = __half22float2(*reinterpret_cast<__half2*>(&r4.x));
            f23 = __half22float2(*reinterpret_cast<__half2*>(&r4.y));
            a4.x += f01.x; a4.y += f01.y; a4.z += f23.x; a4.w += f23.y;
            f01 = __half22float2(*reinterpret_cast<__half2*>(&r5.x));
            f23 = __half22float2(*reinterpret_cast<__half2*>(&r5.y));
            a5.x += f01.x; a5.y += f01.y; a5.z += f23.x; a5.w += f23.y;
            f01 = __half22float2(*reinterpret_cast<__half2*>(&r6.x));
            f23 = __half22float2(*reinterpret_cast<__half2*>(&r6.y));
            a6.x += f01.x; a6.y += f01.y; a6.z += f23.x; a6.w += f23.y;
            f01 = __half22float2(*reinterpret_cast<__half2*>(&r7.x));
            f23 = __half22float2(*reinterpret_cast<__half2*>(&r7.y));
            a7.x += f01.x; a7.y += f01.y; a7.z += f23.x; a7.w += f23.y;
        }
#pragma unroll 1
        for (; j < n; ++j) {
            int s = __shfl_sync(0xffffffffu, idx, j);
            uint2 r = reinterpret_cast<const uint2*>(feat16 + (size_t)s * DIMF)[lane];
            float2 f01 = __half22float2(*reinterpret_cast<__half2*>(&r.x));
            float2 f23 = __half22float2(*reinterpret_cast<__half2*>(&r.y));
            a0.x += f01.x; a0.y += f01.y; a0.z += f23.x; a0.w += f23.y;
        }
    }

    const float inv = __frcp_rn(fmaxf((float)degc, 1.f));
    float4 acc;
    acc.x = ((a0.x + a1.x) + (a2.x + a3.x) + ((a4.x + a5.x) + (a6.x + a7.x))) * inv;
    acc.y = ((a0.y + a1.y) + (a2.y + a3.y) + ((a4.y + a5.y) + (a6.y + a7.y))) * inv;
    acc.z = ((a0.z + a1.z) + (a2.z + a3.z) + ((a4.z + a5.z) + (a6.z + a7.z))) * inv;
    acc.w = ((a0.w + a1.w) + (a2.w + a3.w) + ((a4.w + a5.w) + (a6.w + a7.w))) * inv;
    __half2 h01 = __floats2half2_rn(acc.x, acc.y);
    __half2 h23 = __floats2half2_rn(acc.z, acc.w);
    uint2 packed;
    packed.x = *reinterpret_cast<uint32_t*>(&h01);
    packed.y = *reinterpret_cast<uint32_t*>(&h23);
    reinterpret_cast<uint2*>(g_mh + (size_t)w * DIMF)[lane] = packed;
}

// ---------------------------------------------------------------------------
// fp16 tensor-core GEMM (m16n8k16), BM=128, WEIGHTS RESIDENT IN SMEM:
//   out[m][n] = relu( sum_k A0h[m][k]*W0h[n][k] + sum_k A1h[m][k]*W1h[n][k] + bias[n] )
// Both 128x128 fp16 W matrices preloaded once (64KB+pad); k-loop stages only
// 4KB A tiles (one uint4/thread), double-buffered, 1 sync/tile.
// Dynamic smem 80KB/CTA -> 2 CTAs/SM.
// ---------------------------------------------------------------------------
#define BM  128
#define LDA 24     // A-tile row stride in halves (48B, conflict-free frags)
#define LDB 136    // B row stride in halves (272B, conflict-free frags)
#define SMEM_B_HALVES (2 * 128 * LDB)
#define SMEM_A_HALVES (2 * 128 * LDA)
#define SMEM_BYTES ((SMEM_B_HALVES + SMEM_A_HALVES) * 2)

__global__ __launch_bounds__(256, 2) void gemm_tc_kernel(
        const __half* __restrict__ A0h, const __half* __restrict__ A1h,
        const __half* __restrict__ W0h, const __half* __restrict__ W1h,
        const float* __restrict__ bias, float* __restrict__ out,
        __half* out16) {
    extern __shared__ __half smem[];
    __half* Bw = smem;                     // [2][128][LDB]
    __half* As = smem + SMEM_B_HALVES;     // [2][128][LDA]

    const int tid   = threadIdx.x;
    const int m0    = blockIdx.x * BM;
    const int lane  = tid & 31;
    const int warp  = tid >> 5;
    const int warpM = warp & 1;        // 0..1 -> 64 rows each
    const int warpN = warp >> 1;       // 0..3 -> 32 cols each
    const int lr    = lane >> 2;       // 0..7
    const int lc    = lane & 3;        // 0..3

    // A-tile staging: thread covers row ar, 8-half chunk ac
    const int ar = tid >> 1;           // 0..127
    const int ac = (tid & 1) * 8;      // 0 or 8
    const int gar = m0 + ar;

    float acc[4][4][4];
#pragma unroll
    for (int i = 0; i < 4; ++i)
#pragma unroll
        for (int j = 0; j < 4; ++j)
#pragma unroll
            for (int f = 0; f < 4; ++f) acc[i][j][f] = 0.f;

    uint4 aP;
    auto load_tile = [&](int kt) {
        const __half* A = (kt < 8) ? A0h : A1h;
        const int k0 = (kt & 7) * 16 + ac;
        aP = (gar < N_NODES)
            ? *reinterpret_cast<const uint4*>(A + (size_t)gar * DIMF + k0)
            : make_uint4(0u, 0u, 0u, 0u);
    };
    auto store_tile = [&](int buf) {
        *reinterpret_cast<uint4*>(&As[buf * 128 * LDA + ar * LDA + ac]) = aP;
    };

    // preload both weight matrices into smem (once)
#pragma unroll
    for (int op = 0; op < 2; ++op) {
        const __half* W = op ? W1h : W0h;
#pragma unroll
        for (int i = 0; i < 8; ++i) {
            int u   = tid + i * 256;        // 0..2047
            int row = u >> 4;
            int ch  = (u & 15) * 8;
            uint4 v = *reinterpret_cast<const uint4*>(W + row * DIMF + ch);
            *reinterpret_cast<uint4*>(&Bw[op * 128 * LDB + row * LDB + ch]) = v;
        }
    }
    load_tile(0);
    store_tile(0);
    __syncthreads();

#pragma unroll 1
    for (int kt = 0; kt < 16; ++kt) {
        const int buf = kt & 1;
        if (kt < 15) load_tile(kt + 1);    // LDG hides under MMA

        const __half* Bop = Bw + (kt < 8 ? 0 : 128 * LDB);
        const int k0 = (kt & 7) * 16;

        uint32_t bf0[4], bf1[4];
#pragma unroll
        for (int nt = 0; nt < 4; ++nt) {
            const int n = warpN * 32 + nt * 8 + lr;
            bf0[nt] = *reinterpret_cast<const uint32_t*>(&Bop[n * LDB + k0 + 2 * lc]);
            bf1[nt] = *reinterpret_cast<const uint32_t*>(&Bop[n * LDB + k0 + 2 * lc + 8]);
        }
        const __half* At = As + buf * 128 * LDA;
#pragma unroll
        for (int mt = 0; mt < 4; ++mt) {
            const int m = warpM * 64 + mt * 16 + lr;
            uint32_t a0 = *reinterpret_cast<const uint32_t*>(&At[m * LDA + 2 * lc]);
            uint32_t a1 = *reinterpret_cast<const uint32_t*>(&At[(m + 8) * LDA + 2 * lc]);
            uint32_t a2 = *reinterpret_cast<const uint32_t*>(&At[m * LDA + 2 * lc + 8]);
            uint32_t a3 = *reinterpret_cast<const uint32_t*>(&At[(m + 8) * LDA + 2 * lc + 8]);
#pragma unroll
            for (int nt = 0; nt < 4; ++nt) {
                asm volatile(
                    "mma.sync.aligned.m16n8k16.row.col.f32.f16.f16.f32 "
                    "{%0,%1,%2,%3}, {%4,%5,%6,%7}, {%8,%9}, {%0,%1,%2,%3};"
                    : "+f"(acc[mt][nt][0]), "+f"(acc[mt][nt][1]),
                      "+f"(acc[mt][nt][2]), "+f"(acc[mt][nt][3])
                    : "r"(a0), "r"(a1), "r"(a2), "r"(a3),
                      "r"(bf0[nt]), "r"(bf1[nt]));
            }
        }

        if (kt < 15) {
            store_tile(buf ^ 1);
            __syncthreads();
        }
    }

    // epilogue: + bias, relu; fp32 out and/or fp16 shadow (each nullable)
#pragma unroll
    for (int nt = 0; nt < 4; ++nt) {
        const int n = warpN * 32 + nt * 8 + 2 * lc;
        const float bv0 = __ldg(&bias[n]);
        const float bv1 = __ldg(&bias[n + 1]);
#pragma unroll
        for (int mt = 0; mt < 4; ++mt) {
            const int r = m0 + warpM * 64 + mt * 16 + lr;
            if (r < N_NODES) {
                float vx = fmaxf(acc[mt][nt][0] + bv0, 0.f);
                float vy = fmaxf(acc[mt][nt][1] + bv1, 0.f);
                if (out) {
                    float2 v = make_float2(vx, vy);
                    *reinterpret_cast<float2*>(out + (size_t)r * DIMF + n) = v;
                }
                if (out16)
                    *reinterpret_cast<__half2*>(out16 + (size_t)r * DIMF + n) =
                        __floats2half2_rn(vx, vy);
            }
            if (r + 8 < N_NODES) {
                float vx = fmaxf(acc[mt][nt][2] + bv0, 0.f);
                float vy = fmaxf(acc[mt][nt][3] + bv1, 0.f);
                if (out) {
                    float2 v = make_float2(vx, vy);
                    *reinterpret_cast<float2*>(out + (size_t)(r + 8) * DIMF + n) = v;
                }
                if (out16)
                    *reinterpret_cast<__half2*>(out16 + (size_t)(r + 8) * DIMF + n) =
                        __floats2half2_rn(vx, vy);
            }
        }
    }
}

// ---------------------------------------------------------------------------
// launch
// ---------------------------------------------------------------------------
extern "C" void kernel_launch(void* const* d_in, const int* in_sizes, int n_in,
                              void* d_out, int out_size) {
    const float* x   = (const float*)d_in[0];
    const int*   ei  = (const int*)d_in[1];
    const float* W1l = (const float*)d_in[2];
    const float* b1l = (const float*)d_in[3];
    const float* W1r = (const float*)d_in[4];
    const float* W2l = (const float*)d_in[5];
    const float* b2l = (const float*)d_in[6];
    const float* W2r = (const float*)d_in[7];
    float* out = (float*)d_out;

    const int tot4      = N_NODES * DIMF / 4;
    const int prep_grid = (tot4 + 255) / 256;
    const int edge_grid = (N_EDGES + 255) / 256;
    const int agg_grid  = (N_NODES + 7) / 8;              // warp per node
    const int gemm_grid = (N_NODES + BM - 1) / BM;        // 313
    const int wconv_grid = (4 * DIMF * DIMF / 8 + 255) / 256;

    static __half* p_mh = nullptr;
    static __half* p_xh = nullptr;
    static __half* p_hh = nullptr;
    static __half* p_wh = nullptr;
    if (!p_mh) {
        cudaGetSymbolAddress((void**)&p_mh, g_mh);
        cudaGetSymbolAddress((void**)&p_xh, g_xh);
        cudaGetSymbolAddress((void**)&p_hh, g_hh);
        cudaGetSymbolAddress((void**)&p_wh, g_wh);
        cudaFuncSetAttribute(gemm_tc_kernel,
                             cudaFuncAttributeMaxDynamicSharedMemorySize, SMEM_BYTES);
    }
    const int WSZ = DIMF * DIMF;
    __half* w1l_h = p_wh;
    __half* w1r_h = p_wh + WSZ;
    __half* w2l_h = p_wh + 2 * WSZ;
    __half* w2r_h = p_wh + 3 * WSZ;

    // ---- prep + weight cvt + padded-CSR build ----
    prep_kernel<<<prep_grid, 256>>>(x);
    prep_w_kernel<<<wconv_grid, 256>>>(W1l, W1r, W2l, W2r);
    sort_kernel<<<edge_grid, 256>>>(ei);

    // ---- layer 1 (fp32 out not needed; only fp16 shadow) ----
    agg_kernel<<<agg_grid, 256>>>(p_xh);
    gemm_tc_kernel<<<gemm_grid, 256, SMEM_BYTES>>>(p_mh, p_xh, w1l_h, w1r_h,
                                                   b1l, nullptr, p_hh);

    // ---- layer 2 ----
    agg_kernel<<<agg_grid, 256>>>(p_hh);
    gemm_tc_kernel<<<gemm_grid, 256, SMEM_BYTES>>>(p_mh, p_hh, w2l_h, w2r_h,
                                                   b2l, out, nullptr);
}

// round 15
// speedup vs baseline: 1.8514x; 1.2297x over previous
#include <cuda_runtime.h>
#include <cuda_fp16.h>
#include <cstdint>

#define N_NODES 40000
#define DIMF    128
#define N_EDGES 640000
#define CAP     96            // max supported in-degree (Poisson(16): P(>=96)~0)

// ---- scratch (no allocs allowed) ----
__device__ int    g_cur[N_NODES];           // sort cursors == degree after sort
__device__ int    g_esrc[N_NODES * CAP];    // src ids, padded CSR (15.4 MB)
__device__ __half g_mh[N_NODES * DIMF];     // fp16 neighbor-MEAN (GEMM A0)
__device__ __half g_xh[N_NODES * DIMF];     // fp16 shadow of x
__device__ __half g_hh[N_NODES * DIMF];     // fp16 shadow of h
__device__ __half g_wh[4 * DIMF * DIMF];    // fp16 weights: W1l, W1r, W2l, W2r

// ---------------------------------------------------------------------------
// prep: x -> fp16 shadow; zero cursors.
// ---------------------------------------------------------------------------
__global__ void prep_kernel(const float* __restrict__ x) {
    int i = blockIdx.x * blockDim.x + threadIdx.x;      // float4 index
    const int tot4 = N_NODES * DIMF / 4;
    if (i < tot4) {
        float4 v = reinterpret_cast<const float4*>(x)[i];
        __half2 h01 = __floats2half2_rn(v.x, v.y);
        __half2 h23 = __floats2half2_rn(v.z, v.w);
        uint2 packed;
        packed.x = *reinterpret_cast<uint32_t*>(&h01);
        packed.y = *reinterpret_cast<uint32_t*>(&h23);
        reinterpret_cast<uint2*>(g_xh)[i] = packed;
    }
    if (i < N_NODES) g_cur[i] = 0;
}

// convert the 4 weight matrices (128x128 fp32 each) to fp16 once
__global__ void prep_w_kernel(const float* __restrict__ w0,
                              const float* __restrict__ w1,
                              const float* __restrict__ w2,
                              const float* __restrict__ w3) {
    int i = blockIdx.x * blockDim.x + threadIdx.x;      // 8-half chunk id
    const int per = DIMF * DIMF / 8;                    // 2048 chunks/matrix
    if (i >= 4 * per) return;
    const float* src = (i < per) ? w0 : (i < 2 * per) ? w1 : (i < 3 * per) ? w2 : w3;
    int rem = i & (per - 1);
    float4 a = reinterpret_cast<const float4*>(src)[rem * 2];
    float4 b = reinterpret_cast<const float4*>(src)[rem * 2 + 1];
    __half2 h0 = __floats2half2_rn(a.x, a.y), h1 = __floats2half2_rn(a.z, a.w);
    __half2 h2 = __floats2half2_rn(b.x, b.y), h3 = __floats2half2_rn(b.z, b.w);
    uint4 p;
    p.x = *reinterpret_cast<uint32_t*>(&h0);
    p.y = *reinterpret_cast<uint32_t*>(&h1);
    p.z = *reinterpret_cast<uint32_t*>(&h2);
    p.w = *reinterpret_cast<uint32_t*>(&h3);
    reinterpret_cast<uint4*>(g_wh)[i] = p;
}

// ---------------------------------------------------------------------------
// padded-CSR counting sort. Cursor end-value == degree (no hist, no scan).
// ---------------------------------------------------------------------------
__global__ void sort_kernel(const int* __restrict__ ei) {
    int e = blockIdx.x * blockDim.x + threadIdx.x;
    if (e >= N_EDGES) return;
    int s = ei[e];
    int d = ei[N_EDGES + e];
    if ((unsigned)s >= N_NODES || (unsigned)d >= N_NODES) return;
    int pos = atomicAdd(&g_cur[d], 1);
    if (pos < CAP) g_esrc[d * CAP + pos] = s;
}

// ---------------------------------------------------------------------------
// aggregate (gather): one warp per dst node. Per 8-neighbor group: 8 fp16
// LDG.64 (MLP=8), HADD2 pairwise tree (depth 3), ONE fp16->fp32 convert+add.
// Cross-group accumulation stays fp32. Emits fp16 MEAN directly.
// ---------------------------------------------------------------------------
__global__ __launch_bounds__(256) void agg_kernel(const __half* __restrict__ feat16) {
    const int w    = blockIdx.x * 8 + (threadIdx.x >> 5);
    const int lane = threadIdx.x & 31;
    if (w >= N_NODES) return;

    const int degc  = g_cur[w];
    const int deg   = min(degc, CAP);
    const int start = w * CAP;

    float4 acc = make_float4(0.f, 0.f, 0.f, 0.f);

    for (int base = 0; base < deg; base += 32) {
        const int n = min(32, deg - base);
        int idx = __ldg(&g_esrc[start + base + lane]);

        int j = 0;
        const int full = n & ~7;
#pragma unroll 1
        for (; j < full; j += 8) {
            int s0 = __shfl_sync(0xffffffffu, idx, j + 0);
            int s1 = __shfl_sync(0xffffffffu, idx, j + 1);
            int s2 = __shfl_sync(0xffffffffu, idx, j + 2);
            int s3 = __shfl_sync(0xffffffffu, idx, j + 3);
            int s4 = __shfl_sync(0xffffffffu, idx, j + 4);
            int s5 = __shfl_sync(0xffffffffu, idx, j + 5);
            int s6 = __shfl_sync(0xffffffffu, idx, j + 6);
            int s7 = __shfl_sync(0xffffffffu, idx, j + 7);
            uint2 r0 = reinterpret_cast<const uint2*>(feat16 + (size_t)s0 * DIMF)[lane];
            uint2 r1 = reinterpret_cast<const uint2*>(feat16 + (size_t)s1 * DIMF)[lane];
            uint2 r2 = reinterpret_cast<const uint2*>(feat16 + (size_t)s2 * DIMF)[lane];
            uint2 r3 = reinterpret_cast<const uint2*>(feat16 + (size_t)s3 * DIMF)[lane];
            uint2 r4 = reinterpret_cast<const uint2*>(feat16 + (size_t)s4 * DIMF)[lane];
            uint2 r5 = reinterpret_cast<const uint2*>(feat16 + (size_t)s5 * DIMF)[lane];
            uint2 r6 = reinterpret_cast<const uint2*>(feat16 + (size_t)s6 * DIMF)[lane];
            uint2 r7 = reinterpret_cast<const uint2*>(feat16 + (size_t)s7 * DIMF)[lane];
            // pairwise HADD2 tree over the 8 rows (depth 3), both half2 slots
            __half2 lo = __hadd2(
                __hadd2(__hadd2(*reinterpret_cast<__half2*>(&r0.x),
                                *reinterpret_cast<__half2*>(&r1.x)),
                        __hadd2(*reinterpret_cast<__half2*>(&r2.x),
                                *reinterpret_cast<__half2*>(&r3.x))),
                __hadd2(__hadd2(*reinterpret_cast<__half2*>(&r4.x),
                                *reinterpret_cast<__half2*>(&r5.x)),
                        __hadd2(*reinterpret_cast<__half2*>(&r6.x),
                                *reinterpret_cast<__half2*>(&r7.x))));
            __half2 hi = __hadd2(
                __hadd2(__hadd2(*reinterpret_cast<__half2*>(&r0.y),
                                *reinterpret_cast<__half2*>(&r1.y)),
                        __hadd2(*reinterpret_cast<__half2*>(&r2.y),
                                *reinterpret_cast<__half2*>(&r3.y))),
                __hadd2(__hadd2(*reinterpret_cast<__half2*>(&r4.y),
                                *reinterpret_cast<__half2*>(&r5.y)),
                        __hadd2(*reinterpret_cast<__half2*>(&r6.y),
                                *reinterpret_cast<__half2*>(&r7.y))));
            float2 f01 = __half22float2(lo);
            float2 f23 = __half22float2(hi);
            acc.x += f01.x; acc.y += f01.y; acc.z += f23.x; acc.w += f23.y;
        }
#pragma unroll 1
        for (; j < n; ++j) {        // tail: fp32 adds (no extra fp16 rounding)
            int s = __shfl_sync(0xffffffffu, idx, j);
            uint2 r = reinterpret_cast<const uint2*>(feat16 + (size_t)s * DIMF)[lane];
            float2 f01 = __half22float2(*reinterpret_cast<__half2*>(&r.x));
            float2 f23 = __half22float2(*reinterpret_cast<__half2*>(&r.y));
            acc.x += f01.x; acc.y += f01.y; acc.z += f23.x; acc.w += f23.y;
        }
    }

    const float inv = __frcp_rn(fmaxf((float)degc, 1.f));
    __half2 h01 = __floats2half2_rn(acc.x * inv, acc.y * inv);
    __half2 h23 = __floats2half2_rn(acc.z * inv, acc.w * inv);
    uint2 packed;
    packed.x = *reinterpret_cast<uint32_t*>(&h01);
    packed.y = *reinterpret_cast<uint32_t*>(&h23);
    reinterpret_cast<uint2*>(g_mh + (size_t)w * DIMF)[lane] = packed;
}

// ---------------------------------------------------------------------------
// fp16 tensor-core GEMM (m16n8k16), BM=128, WEIGHTS RESIDENT IN SMEM:
//   out[m][n] = relu( sum_k A0h[m][k]*W0h[n][k] + sum_k A1h[m][k]*W1h[n][k] + bias[n] )
// Both 128x128 fp16 W matrices preloaded once; k-loop stages only 4KB A tiles
// (one uint4/thread), double-buffered, 1 sync/tile. 80KB smem -> 2 CTAs/SM.
// ---------------------------------------------------------------------------
#define BM  128
#define LDA 24     // A-tile row stride in halves (48B, conflict-free frags)
#define LDB 136    // B row stride in halves (272B, conflict-free frags)
#define SMEM_B_HALVES (2 * 128 * LDB)
#define SMEM_A_HALVES (2 * 128 * LDA)
#define SMEM_BYTES ((SMEM_B_HALVES + SMEM_A_HALVES) * 2)

__global__ __launch_bounds__(256, 2) void gemm_tc_kernel(
        const __half* __restrict__ A0h, const __half* __restrict__ A1h,
        const __half* __restrict__ W0h, const __half* __restrict__ W1h,
        const float* __restrict__ bias, float* __restrict__ out,
        __half* out16) {
    extern __shared__ __half smem[];
    __half* Bw = smem;                     // [2][128][LDB]
    __half* As = smem + SMEM_B_HALVES;     // [2][128][LDA]

    const int tid   = threadIdx.x;
    const int m0    = blockIdx.x * BM;
    const int lane  = tid & 31;
    const int warp  = tid >> 5;
    const int warpM = warp & 1;        // 0..1 -> 64 rows each
    const int warpN = warp >> 1;       // 0..3 -> 32 cols each
    const int lr    = lane >> 2;       // 0..7
    const int lc    = lane & 3;        // 0..3

    const int ar = tid >> 1;           // 0..127
    const int ac = (tid & 1) * 8;      // 0 or 8
    const int gar = m0 + ar;

    float acc[4][4][4];
#pragma unroll
    for (int i = 0; i < 4; ++i)
#pragma unroll
        for (int j = 0; j < 4; ++j)
#pragma unroll
            for (int f = 0; f < 4; ++f) acc[i][j][f] = 0.f;

    uint4 aP;
    auto load_tile = [&](int kt) {
        const __half* A = (kt < 8) ? A0h : A1h;
        const int k0 = (kt & 7) * 16 + ac;
        aP = (gar < N_NODES)
            ? *reinterpret_cast<const uint4*>(A + (size_t)gar * DIMF + k0)
            : make_uint4(0u, 0u, 0u, 0u);
    };
    auto store_tile = [&](int buf) {
        *reinterpret_cast<uint4*>(&As[buf * 128 * LDA + ar * LDA + ac]) = aP;
    };

    // preload both weight matrices into smem (once)
#pragma unroll
    for (int op = 0; op < 2; ++op) {
        const __half* W = op ? W1h : W0h;
#pragma unroll
        for (int i = 0; i < 8; ++i) {
            int u   = tid + i * 256;        // 0..2047
            int row = u >> 4;
            int ch  = (u & 15) * 8;
            uint4 v = *reinterpret_cast<const uint4*>(W + row * DIMF + ch);
            *reinterpret_cast<uint4*>(&Bw[op * 128 * LDB + row * LDB + ch]) = v;
        }
    }
    load_tile(0);
    store_tile(0);
    __syncthreads();

#pragma unroll 1
    for (int kt = 0; kt < 16; ++kt) {
        const int buf = kt & 1;
        if (kt < 15) load_tile(kt + 1);    // LDG hides under MMA

        const __half* Bop = Bw + (kt < 8 ? 0 : 128 * LDB);
        const int k0 = (kt & 7) * 16;

        uint32_t bf0[4], bf1[4];
#pragma unroll
        for (int nt = 0; nt < 4; ++nt) {
            const int n = warpN * 32 + nt * 8 + lr;
            bf0[nt] = *reinterpret_cast<const uint32_t*>(&Bop[n * LDB + k0 + 2 * lc]);
            bf1[nt] = *reinterpret_cast<const uint32_t*>(&Bop[n * LDB + k0 + 2 * lc + 8]);
        }
        const __half* At = As + buf * 128 * LDA;
#pragma unroll
        for (int mt = 0; mt < 4; ++mt) {
            const int m = warpM * 64 + mt * 16 + lr;
            uint32_t a0 = *reinterpret_cast<const uint32_t*>(&At[m * LDA + 2 * lc]);
            uint32_t a1 = *reinterpret_cast<const uint32_t*>(&At[(m + 8) * LDA + 2 * lc]);
            uint32_t a2 = *reinterpret_cast<const uint32_t*>(&At[m * LDA + 2 * lc + 8]);
            uint32_t a3 = *reinterpret_cast<const uint32_t*>(&At[(m + 8) * LDA + 2 * lc + 8]);
#pragma unroll
            for (int nt = 0; nt < 4; ++nt) {
                asm volatile(
                    "mma.sync.aligned.m16n8k16.row.col.f32.f16.f16.f32 "
                    "{%0,%1,%2,%3}, {%4,%5,%6,%7}, {%8,%9}, {%0,%1,%2,%3};"
                    : "+f"(acc[mt][nt][0]), "+f"(acc[mt][nt][1]),
                      "+f"(acc[mt][nt][2]), "+f"(acc[mt][nt][3])
                    : "r"(a0), "r"(a1), "r"(a2), "r"(a3),
                      "r"(bf0[nt]), "r"(bf1[nt]));
            }
        }

        if (kt < 15) {
            store_tile(buf ^ 1);
            __syncthreads();
        }
    }

    // epilogue: + bias, relu; fp32 out and/or fp16 shadow (each nullable)
#pragma unroll
    for (int nt = 0; nt < 4; ++nt) {
        const int n = warpN * 32 + nt * 8 + 2 * lc;
        const float bv0 = __ldg(&bias[n]);
        const float bv1 = __ldg(&bias[n + 1]);
#pragma unroll
        for (int mt = 0; mt < 4; ++mt) {
            const int r = m0 + warpM * 64 + mt * 16 + lr;
            if (r < N_NODES) {
                float vx = fmaxf(acc[mt][nt][0] + bv0, 0.f);
                float vy = fmaxf(acc[mt][nt][1] + bv1, 0.f);
                if (out) {
                    float2 v = make_float2(vx, vy);
                    *reinterpret_cast<float2*>(out + (size_t)r * DIMF + n) = v;
                }
                if (out16)
                    *reinterpret_cast<__half2*>(out16 + (size_t)r * DIMF + n) =
                        __floats2half2_rn(vx, vy);
            }
            if (r + 8 < N_NODES) {
                float vx = fmaxf(acc[mt][nt][2] + bv0, 0.f);
                float vy = fmaxf(acc[mt][nt][3] + bv1, 0.f);
                if (out) {
                    float2 v = make_float2(vx, vy);
                    *reinterpret_cast<float2*>(out + (size_t)(r + 8) * DIMF + n) = v;
                }
                if (out16)
                    *reinterpret_cast<__half2*>(out16 + (size_t)(r + 8) * DIMF + n) =
                        __floats2half2_rn(vx, vy);
            }
        }
    }
}

// ---------------------------------------------------------------------------
// launch
// ---------------------------------------------------------------------------
extern "C" void kernel_launch(void* const* d_in, const int* in_sizes, int n_in,
                              void* d_out, int out_size) {
    const float* x   = (const float*)d_in[0];
    const int*   ei  = (const int*)d_in[1];
    const float* W1l = (const float*)d_in[2];
    const float* b1l = (const float*)d_in[3];
    const float* W1r = (const float*)d_in[4];
    const float* W2l = (const float*)d_in[5];
    const float* b2l = (const float*)d_in[6];
    const float* W2r = (const float*)d_in[7];
    float* out = (float*)d_out;

    const int tot4      = N_NODES * DIMF / 4;
    const int prep_grid = (tot4 + 255) / 256;
    const int edge_grid = (N_EDGES + 255) / 256;
    const int agg_grid  = (N_NODES + 7) / 8;              // warp per node
    const int gemm_grid = (N_NODES + BM - 1) / BM;        // 313
    const int wconv_grid = (4 * DIMF * DIMF / 8 + 255) / 256;

    static __half* p_mh = nullptr;
    static __half* p_xh = nullptr;
    static __half* p_hh = nullptr;
    static __half* p_wh = nullptr;
    if (!p_mh) {
        cudaGetSymbolAddress((void**)&p_mh, g_mh);
        cudaGetSymbolAddress((void**)&p_xh, g_xh);
        cudaGetSymbolAddress((void**)&p_hh, g_hh);
        cudaGetSymbolAddress((void**)&p_wh, g_wh);
        cudaFuncSetAttribute(gemm_tc_kernel,
                             cudaFuncAttributeMaxDynamicSharedMemorySize, SMEM_BYTES);
    }
    const int WSZ = DIMF * DIMF;
    __half* w1l_h = p_wh;
    __half* w1r_h = p_wh + WSZ;
    __half* w2l_h = p_wh + 2 * WSZ;
    __half* w2r_h = p_wh + 3 * WSZ;

    // ---- prep + weight cvt + padded-CSR build ----
    prep_kernel<<<prep_grid, 256>>>(x);
    prep_w_kernel<<<wconv_grid, 256>>>(W1l, W1r, W2l, W2r);
    sort_kernel<<<edge_grid, 256>>>(ei);

    // ---- layer 1 (only fp16 shadow needed) ----
    agg_kernel<<<agg_grid, 256>>>(p_xh);
    gemm_tc_kernel<<<gemm_grid, 256, SMEM_BYTES>>>(p_mh, p_xh, w1l_h, w1r_h,
                                                   b1l, nullptr, p_hh);

    // ---- layer 2 ----
    agg_kernel<<<agg_grid, 256>>>(p_hh);
    gemm_tc_kernel<<<gemm_grid, 256, SMEM_BYTES>>>(p_mh, p_hh, w2l_h, w2r_h,
                                                   b2l, out, nullptr);
}

// round 16
// speedup vs baseline: 2.0240x; 1.0933x over previous
#include <cuda_runtime.h>
#include <cuda_fp16.h>
#include <cstdint>

#define N_NODES 40000
#define DIMF    128
#define N_EDGES 640000
#define CAP     96            // max supported in-degree (Poisson(16): P(>=96)~0)

// ---- scratch (no allocs allowed) ----
__device__ int    g_cur[N_NODES];           // sort cursors == degree after sort
__device__ int    g_esrc[N_NODES * CAP];    // src ids, padded CSR (15.4 MB)
__device__ __half g_mh[N_NODES * DIMF];     // fp16 neighbor-MEAN (GEMM A0)
__device__ __half g_xh[N_NODES * DIMF];     // fp16 shadow of x
__device__ __half g_hh[N_NODES * DIMF];     // fp16 shadow of h
__device__ __half g_wh[4 * DIMF * DIMF];    // fp16 weights: W1l, W1r, W2l, W2r

// ---------------------------------------------------------------------------
// prep: x -> fp16 shadow; zero cursors; convert 4 weight mats to fp16.
// ---------------------------------------------------------------------------
__global__ void prep_kernel(const float* __restrict__ x,
                            const float* __restrict__ w0,
                            const float* __restrict__ w1,
                            const float* __restrict__ w2,
                            const float* __restrict__ w3) {
    int i = blockIdx.x * blockDim.x + threadIdx.x;      // float4 index
    const int tot4 = N_NODES * DIMF / 4;
    if (i < tot4) {
        float4 v = reinterpret_cast<const float4*>(x)[i];
        __half2 h01 = __floats2half2_rn(v.x, v.y);
        __half2 h23 = __floats2half2_rn(v.z, v.w);
        uint2 packed;
        packed.x = *reinterpret_cast<uint32_t*>(&h01);
        packed.y = *reinterpret_cast<uint32_t*>(&h23);
        reinterpret_cast<uint2*>(g_xh)[i] = packed;
    }
    if (i < N_NODES) g_cur[i] = 0;
    // weight conversion: 4 mats x 2048 8-half chunks
    const int per = DIMF * DIMF / 8;                    // 2048
    if (i < 4 * per) {
        const float* src = (i < per) ? w0 : (i < 2 * per) ? w1
                          : (i < 3 * per) ? w2 : w3;
        int rem = i & (per - 1);
        float4 a = reinterpret_cast<const float4*>(src)[rem * 2];
        float4 b = reinterpret_cast<const float4*>(src)[rem * 2 + 1];
        __half2 h0 = __floats2half2_rn(a.x, a.y), h1 = __floats2half2_rn(a.z, a.w);
        __half2 h2 = __floats2half2_rn(b.x, b.y), h3 = __floats2half2_rn(b.z, b.w);
        uint4 p;
        p.x = *reinterpret_cast<uint32_t*>(&h0);
        p.y = *reinterpret_cast<uint32_t*>(&h1);
        p.z = *reinterpret_cast<uint32_t*>(&h2);
        p.w = *reinterpret_cast<uint32_t*>(&h3);
        reinterpret_cast<uint4*>(g_wh)[i] = p;
    }
}

// ---------------------------------------------------------------------------
// padded-CSR counting sort: 4 edges/thread (2x LDG.128 idx, 4 indep atomics,
// 4 stores -> MLP=4 instead of 1).
// ---------------------------------------------------------------------------
__global__ void sort_kernel(const int* __restrict__ ei) {
    int t  = blockIdx.x * blockDim.x + threadIdx.x;
    int e0 = t * 4;
    if (e0 >= N_EDGES) return;
    int4 s4 = *reinterpret_cast<const int4*>(ei + e0);
    int4 d4 = *reinterpret_cast<const int4*>(ei + N_EDGES + e0);
    int s[4] = {s4.x, s4.y, s4.z, s4.w};
    int d[4] = {d4.x, d4.y, d4.z, d4.w};
    int pos[4];
#pragma unroll
    for (int k = 0; k < 4; ++k)
        pos[k] = ((unsigned)d[k] < N_NODES) ? atomicAdd(&g_cur[d[k]], 1) : CAP;
#pragma unroll
    for (int k = 0; k < 4; ++k)
        if ((unsigned)s[k] < N_NODES && pos[k] < CAP)
            g_esrc[d[k] * CAP + pos[k]] = s[k];
}

// ---------------------------------------------------------------------------
// aggregate (gather): one warp per dst node. Per 8-neighbor group: 8 fp16
// LDG.64 (MLP=8), HADD2 pairwise tree (depth 3), ONE fp16->fp32 convert+add.
// Cross-group accumulation stays fp32. Emits fp16 MEAN directly.
// ---------------------------------------------------------------------------
__global__ __launch_bounds__(256) void agg_kernel(const __half* __restrict__ feat16) {
    const int w    = blockIdx.x * 8 + (threadIdx.x >> 5);
    const int lane = threadIdx.x & 31;
    if (w >= N_NODES) return;

    const int degc  = g_cur[w];
    const int deg   = min(degc, CAP);
    const int start = w * CAP;

    float4 acc = make_float4(0.f, 0.f, 0.f, 0.f);

    for (int base = 0; base < deg; base += 32) {
        const int n = min(32, deg - base);
        int idx = __ldg(&g_esrc[start + base + lane]);

        int j = 0;
        const int full = n & ~7;
#pragma unroll 1
        for (; j < full; j += 8) {
            int s0 = __shfl_sync(0xffffffffu, idx, j + 0);
            int s1 = __shfl_sync(0xffffffffu, idx, j + 1);
            int s2 = __shfl_sync(0xffffffffu, idx, j + 2);
            int s3 = __shfl_sync(0xffffffffu, idx, j + 3);
            int s4 = __shfl_sync(0xffffffffu, idx, j + 4);
            int s5 = __shfl_sync(0xffffffffu, idx, j + 5);
            int s6 = __shfl_sync(0xffffffffu, idx, j + 6);
            int s7 = __shfl_sync(0xffffffffu, idx, j + 7);
            uint2 r0 = reinterpret_cast<const uint2*>(feat16 + (size_t)s0 * DIMF)[lane];
            uint2 r1 = reinterpret_cast<const uint2*>(feat16 + (size_t)s1 * DIMF)[lane];
            uint2 r2 = reinterpret_cast<const uint2*>(feat16 + (size_t)s2 * DIMF)[lane];
            uint2 r3 = reinterpret_cast<const uint2*>(feat16 + (size_t)s3 * DIMF)[lane];
            uint2 r4 = reinterpret_cast<const uint2*>(feat16 + (size_t)s4 * DIMF)[lane];
            uint2 r5 = reinterpret_cast<const uint2*>(feat16 + (size_t)s5 * DIMF)[lane];
            uint2 r6 = reinterpret_cast<const uint2*>(feat16 + (size_t)s6 * DIMF)[lane];
            uint2 r7 = reinterpret_cast<const uint2*>(feat16 + (size_t)s7 * DIMF)[lane];
            __half2 lo = __hadd2(
                __hadd2(__hadd2(*reinterpret_cast<__half2*>(&r0.x),
                                *reinterpret_cast<__half2*>(&r1.x)),
                        __hadd2(*reinterpret_cast<__half2*>(&r2.x),
                                *reinterpret_cast<__half2*>(&r3.x))),
                __hadd2(__hadd2(*reinterpret_cast<__half2*>(&r4.x),
                                *reinterpret_cast<__half2*>(&r5.x)),
                        __hadd2(*reinterpret_cast<__half2*>(&r6.x),
                                *reinterpret_cast<__half2*>(&r7.x))));
            __half2 hi = __hadd2(
                __hadd2(__hadd2(*reinterpret_cast<__half2*>(&r0.y),
                                *reinterpret_cast<__half2*>(&r1.y)),
                        __hadd2(*reinterpret_cast<__half2*>(&r2.y),
                                *reinterpret_cast<__half2*>(&r3.y))),
                __hadd2(__hadd2(*reinterpret_cast<__half2*>(&r4.y),
                                *reinterpret_cast<__half2*>(&r5.y)),
                        __hadd2(*reinterpret_cast<__half2*>(&r6.y),
                                *reinterpret_cast<__half2*>(&r7.y))));
            float2 f01 = __half22float2(lo);
            float2 f23 = __half22float2(hi);
            acc.x += f01.x; acc.y += f01.y; acc.z += f23.x; acc.w += f23.y;
        }
#pragma unroll 1
        for (; j < n; ++j) {
            int s = __shfl_sync(0xffffffffu, idx, j);
            uint2 r = reinterpret_cast<const uint2*>(feat16 + (size_t)s * DIMF)[lane];
            float2 f01 = __half22float2(*reinterpret_cast<__half2*>(&r.x));
            float2 f23 = __half22float2(*reinterpret_cast<__half2*>(&r.y));
            acc.x += f01.x; acc.y += f01.y; acc.z += f23.x; acc.w += f23.y;
        }
    }

    const float inv = __frcp_rn(fmaxf((float)degc, 1.f));
    __half2 h01 = __floats2half2_rn(acc.x * inv, acc.y * inv);
    __half2 h23 = __floats2half2_rn(acc.z * inv, acc.w * inv);
    uint2 packed;
    packed.x = *reinterpret_cast<uint32_t*>(&h01);
    packed.y = *reinterpret_cast<uint32_t*>(&h23);
    reinterpret_cast<uint2*>(g_mh + (size_t)w * DIMF)[lane] = packed;
}

// ---------------------------------------------------------------------------
// fp16 tensor-core GEMM (m16n8k16), BM=128, weights resident in smem,
// A staged TWO k-tiles per buffer (8 syncs instead of 16):
//   out[m][n] = relu( sum_k A0h[m][k]*W0h[n][k] + sum_k A1h[m][k]*W1h[n][k] + bias[n] )
// ---------------------------------------------------------------------------
#define BM   128
#define LDA2 40    // A pair-tile row stride in halves (80B; frag banks verified)
#define LDB  136   // B row stride in halves (272B; frag banks = lane id)
#define SMEM_B_HALVES (2 * 128 * LDB)
#define SMEM_A_HALVES (2 * 128 * LDA2)
#define SMEM_BYTES ((SMEM_B_HALVES + SMEM_A_HALVES) * 2)

__global__ __launch_bounds__(256, 2) void gemm_tc_kernel(
        const __half* __restrict__ A0h, const __half* __restrict__ A1h,
        const __half* __restrict__ W0h, const __half* __restrict__ W1h,
        const float* __restrict__ bias, float* __restrict__ out,
        __half* out16) {
    extern __shared__ __half smem[];
    __half* Bw = smem;                     // [2][128][LDB]
    __half* As = smem + SMEM_B_HALVES;     // [2][128][LDA2]

    const int tid   = threadIdx.x;
    const int m0    = blockIdx.x * BM;
    const int lane  = tid & 31;
    const int warp  = tid >> 5;
    const int warpM = warp & 1;        // 0..1 -> 64 rows each
    const int warpN = warp >> 1;       // 0..3 -> 32 cols each
    const int lr    = lane >> 2;       // 0..7
    const int lc    = lane & 3;        // 0..3

    const int ar = tid >> 1;           // 0..127
    const int ac = (tid & 1) * 8;      // 0 or 8
    const int gar = m0 + ar;

    float acc[4][4][4];
#pragma unroll
    for (int i = 0; i < 4; ++i)
#pragma unroll
        for (int j = 0; j < 4; ++j)
#pragma unroll
            for (int f = 0; f < 4; ++f) acc[i][j][f] = 0.f;

    uint4 aP0, aP1;
    auto load_pair = [&](int p) {      // p = 0..7 (pairs of k-tiles)
        const __half* A = (p < 4) ? A0h : A1h;
        const int k0 = (p & 3) * 32 + ac;
        if (gar < N_NODES) {
            aP0 = *reinterpret_cast<const uint4*>(A + (size_t)gar * DIMF + k0);
            aP1 = *reinterpret_cast<const uint4*>(A + (size_t)gar * DIMF + k0 + 16);
        } else {
            aP0 = make_uint4(0u, 0u, 0u, 0u);
            aP1 = make_uint4(0u, 0u, 0u, 0u);
        }
    };
    auto store_pair = [&](int buf) {
        *reinterpret_cast<uint4*>(&As[buf * 128 * LDA2 + ar * LDA2 + ac])      = aP0;
        *reinterpret_cast<uint4*>(&As[buf * 128 * LDA2 + ar * LDA2 + 16 + ac]) = aP1;
    };

    // preload both weight matrices into smem (once)
#pragma unroll
    for (int op = 0; op < 2; ++op) {
        const __half* W = op ? W1h : W0h;
#pragma unroll
        for (int i = 0; i < 8; ++i) {
            int u   = tid + i * 256;        // 0..2047
            int row = u >> 4;
            int ch  = (u & 15) * 8;
            uint4 v = *reinterpret_cast<const uint4*>(W + row * DIMF + ch);
            *reinterpret_cast<uint4*>(&Bw[op * 128 * LDB + row * LDB + ch]) = v;
        }
    }
    load_pair(0);
    store_pair(0);
    __syncthreads();

#pragma unroll 1
    for (int p = 0; p < 8; ++p) {
        const int buf = p & 1;
        if (p < 7) load_pair(p + 1);       // deep prefetch hides under 32 MMAs

        const __half* Bop = Bw + (p < 4 ? 0 : 128 * LDB);
        const __half* At  = As + buf * 128 * LDA2;

#pragma unroll
        for (int ph = 0; ph < 2; ++ph) {
            const int kb = (p & 3) * 32 + ph * 16;   // B k-offset
            const int ka = ph * 16;                  // A tile k-offset

            uint32_t bf0[4], bf1[4];
#pragma unroll
            for (int nt = 0; nt < 4; ++nt) {
                const int n = warpN * 32 + nt * 8 + lr;
                bf0[nt] = *reinterpret_cast<const uint32_t*>(&Bop[n * LDB + kb + 2 * lc]);
                bf1[nt] = *reinterpret_cast<const uint32_t*>(&Bop[n * LDB + kb + 2 * lc + 8]);
            }
#pragma unroll
            for (int mt = 0; mt < 4; ++mt) {
                const int m = warpM * 64 + mt * 16 + lr;
                uint32_t a0 = *reinterpret_cast<const uint32_t*>(&At[m * LDA2 + ka + 2 * lc]);
                uint32_t a1 = *reinterpret_cast<const uint32_t*>(&At[(m + 8) * LDA2 + ka + 2 * lc]);
                uint32_t a2 = *reinterpret_cast<const uint32_t*>(&At[m * LDA2 + ka + 2 * lc + 8]);
                uint32_t a3 = *reinterpret_cast<const uint32_t*>(&At[(m + 8) * LDA2 + ka + 2 * lc + 8]);
#pragma unroll
                for (int nt = 0; nt < 4; ++nt) {
                    asm volatile(
                        "mma.sync.aligned.m16n8k16.row.col.f32.f16.f16.f32 "
                        "{%0,%1,%2,%3}, {%4,%5,%6,%7}, {%8,%9}, {%0,%1,%2,%3};"
                        : "+f"(acc[mt][nt][0]), "+f"(acc[mt][nt][1]),
                          "+f"(acc[mt][nt][2]), "+f"(acc[mt][nt][3])
                        : "r"(a0), "r"(a1), "r"(a2), "r"(a3),
                          "r"(bf0[nt]), "r"(bf1[nt]));
                }
            }
        }

        if (p < 7) {
            store_pair(buf ^ 1);
            __syncthreads();
        }
    }

    // epilogue: + bias, relu; fp32 out and/or fp16 shadow (each nullable)
#pragma unroll
    for (int nt = 0; nt < 4; ++nt) {
        const int n = warpN * 32 + nt * 8 + 2 * lc;
        const float bv0 = __ldg(&bias[n]);
        const float bv1 = __ldg(&bias[n + 1]);
#pragma unroll
        for (int mt = 0; mt < 4; ++mt) {
            const int r = m0 + warpM * 64 + mt * 16 + lr;
            if (r < N_NODES) {
                float vx = fmaxf(acc[mt][nt][0] + bv0, 0.f);
                float vy = fmaxf(acc[mt][nt][1] + bv1, 0.f);
                if (out) {
                    float2 v = make_float2(vx, vy);
                    *reinterpret_cast<float2*>(out + (size_t)r * DIMF + n) = v;
                }
                if (out16)
                    *reinterpret_cast<__half2*>(out16 + (size_t)r * DIMF + n) =
                        __floats2half2_rn(vx, vy);
            }
            if (r + 8 < N_NODES) {
                float vx = fmaxf(acc[mt][nt][2] + bv0, 0.f);
                float vy = fmaxf(acc[mt][nt][3] + bv1, 0.f);
                if (out) {
                    float2 v = make_float2(vx, vy);
                    *reinterpret_cast<float2*>(out + (size_t)(r + 8) * DIMF + n) = v;
                }
                if (out16)
                    *reinterpret_cast<__half2*>(out16 + (size_t)(r + 8) * DIMF + n) =
                        __floats2half2_rn(vx, vy);
            }
        }
    }
}

// ---------------------------------------------------------------------------
// launch
// ---------------------------------------------------------------------------
extern "C" void kernel_launch(void* const* d_in, const int* in_sizes, int n_in,
                              void* d_out, int out_size) {
    const float* x   = (const float*)d_in[0];
    const int*   ei  = (const int*)d_in[1];
    const float* W1l = (const float*)d_in[2];
    const float* b1l = (const float*)d_in[3];
    const float* W1r = (const float*)d_in[4];
    const float* W2l = (const float*)d_in[5];
    const float* b2l = (const float*)d_in[6];
    const float* W2r = (const float*)d_in[7];
    float* out = (float*)d_out;

    const int tot4      = N_NODES * DIMF / 4;
    const int prep_grid = (tot4 + 255) / 256;
    const int sort_grid = (N_EDGES / 4 + 255) / 256;      // 4 edges/thread
    const int agg_grid  = (N_NODES + 7) / 8;              // warp per node
    const int gemm_grid = (N_NODES + BM - 1) / BM;        // 313

    static __half* p_mh = nullptr;
    static __half* p_xh = nullptr;
    static __half* p_hh = nullptr;
    static __half* p_wh = nullptr;
    if (!p_mh) {
        cudaGetSymbolAddress((void**)&p_mh, g_mh);
        cudaGetSymbolAddress((void**)&p_xh, g_xh);
        cudaGetSymbolAddress((void**)&p_hh, g_hh);
        cudaGetSymbolAddress((void**)&p_wh, g_wh);
        cudaFuncSetAttribute(gemm_tc_kernel,
                             cudaFuncAttributeMaxDynamicSharedMemorySize, SMEM_BYTES);
    }
    const int WSZ = DIMF * DIMF;
    __half* w1l_h = p_wh;
    __half* w1r_h = p_wh + WSZ;
    __half* w2l_h = p_wh + 2 * WSZ;
    __half* w2r_h = p_wh + 3 * WSZ;

    // ---- prep (x shadow + weight cvt + cursor zero), then counting sort ----
    prep_kernel<<<prep_grid, 256>>>(x, W1l, W1r, W2l, W2r);
    sort_kernel<<<sort_grid, 256>>>(ei);

    // ---- layer 1 (only fp16 shadow needed) ----
    agg_kernel<<<agg_grid, 256>>>(p_xh);
    gemm_tc_kernel<<<gemm_grid, 256, SMEM_BYTES>>>(p_mh, p_xh, w1l_h, w1r_h,
                                                   b1l, nullptr, p_hh);

    // ---- layer 2 ----
    agg_kernel<<<agg_grid, 256>>>(p_hh);
    gemm_tc_kernel<<<gemm_grid, 256, SMEM_BYTES>>>(p_mh, p_hh, w2l_h, w2r_h,
                                                   b2l, out, nullptr);
}